// round 1
// baseline (speedup 1.0000x reference)
#include <cuda_runtime.h>

// Problem constants
#define BB 4096
#define DD 1024
#define RR 256
#define TM 32                 // batch rows per CTA
#define NCTA (BB / TM)        // 128
#define NTHR 256
#define SHP 257               // padded row stride for tiles (conflict-free transpose)

// Yoshida-4 coefficients (double-precision literals, truncated to float at use)
#define K_W1 1.3512071919596578
#define K_W0 (-1.7024143839193153)
#define K_C1 ((float)(K_W1 * 0.5))                 // = C4
#define K_C2 ((float)((K_W0 + K_W1) * 0.5))        // = C3
#define K_DT 0.01f

__global__ __launch_bounds__(NTHR, 1)
void yoshida_fused_kernel(const float* __restrict__ x,
                          const float* __restrict__ v,
                          const float* __restrict__ force,
                          const float* __restrict__ U,   // [R][D]
                          const float* __restrict__ W,   // [D][R]
                          float* __restrict__ out)       // [2][B][D]: x_final then v3
{
    extern __shared__ float smem[];
    float* sv = smem;                    // [TM][D]      v tile (master copy, fp32)
    float* sh = sv + TM * DD;            // [TM][SHP]    h^2 tile
    float* st = sh + TM * SHP;           // [32][SHP]    U/W staging tile (transposed)

    const int tid  = threadIdx.x;
    const int row0 = blockIdx.x * TM;

    const int bq = tid >> 5;     // 0..7  (4 batch rows each)  -- warp-uniform
    const int lq = tid & 31;     // 0..31 (r or d lane index)

    // ---- load v tile (coalesced float4) ----
    {
        const float4* vsrc = (const float4*)(v + (size_t)row0 * DD);
        float4* dst = (float4*)sv;
        #pragma unroll 4
        for (int i = tid; i < TM * DD / 4; i += NTHR) dst[i] = vsrc[i];
    }
    __syncthreads();

    const float dcoef_tab[3] = { (float)K_W1 * K_DT, (float)K_W0 * K_DT, (float)K_W1 * K_DT };

    for (int step = 0; step < 3; ++step) {
        // ================= Stage 1: h[b][r] = sum_d U[r][d] * sv[b][d]; sh = h*h ====
        float acc[4][8];
        #pragma unroll
        for (int j = 0; j < 4; ++j)
            #pragma unroll
            for (int i = 0; i < 8; ++i) acc[j][i] = 0.f;

        for (int kt = 0; kt < DD / 32; ++kt) {
            // load U[0:256][kt*32 .. +32] -> st[d_local][r] (transposed, padded)
            {
                const int f4 = tid & 7;       // which float4 of the 32-wide d chunk
                const int rr = tid >> 3;      // base row
                #pragma unroll
                for (int it = 0; it < 8; ++it) {
                    const int r = rr + 32 * it;
                    float4 g = *(const float4*)(U + (size_t)r * DD + kt * 32 + f4 * 4);
                    st[(f4 * 4 + 0) * SHP + r] = g.x;
                    st[(f4 * 4 + 1) * SHP + r] = g.y;
                    st[(f4 * 4 + 2) * SHP + r] = g.z;
                    st[(f4 * 4 + 3) * SHP + r] = g.w;
                }
            }
            __syncthreads();

            const float* svb = sv + (bq * 4) * DD + kt * 32;
            #pragma unroll
            for (int dd2 = 0; dd2 < 32; ++dd2) {
                const float a0 = svb[0 * DD + dd2];
                const float a1 = svb[1 * DD + dd2];
                const float a2 = svb[2 * DD + dd2];
                const float a3 = svb[3 * DD + dd2];
                const float* str = st + dd2 * SHP + lq;
                #pragma unroll
                for (int i = 0; i < 8; ++i) {
                    const float u = str[32 * i];
                    acc[0][i] += a0 * u;
                    acc[1][i] += a1 * u;
                    acc[2][i] += a2 * u;
                    acc[3][i] += a3 * u;
                }
            }
            __syncthreads();
        }
        // write h^2
        #pragma unroll
        for (int j = 0; j < 4; ++j)
            #pragma unroll
            for (int i = 0; i < 8; ++i)
                sh[(bq * 4 + j) * SHP + lq + 32 * i] = acc[j][i] * acc[j][i];
        __syncthreads();

        // ===== Stage 2: Gamma[b][d] = sum_r W[d][r] * sh[b][r], fused v/x update ====
        const float dcoef = dcoef_tab[step];

        for (int nt = 0; nt < 4; ++nt) {       // d-tile of 256
            float acc2[4][8];
            #pragma unroll
            for (int j = 0; j < 4; ++j)
                #pragma unroll
                for (int i = 0; i < 8; ++i) acc2[j][i] = 0.f;

            for (int rt = 0; rt < 8; ++rt) {   // r-tile of 32
                // load W[nt*256 .. +256][rt*32 .. +32] -> st[r_local][d_local]
                {
                    const int f4 = tid & 7;
                    const int dl0 = tid >> 3;
                    #pragma unroll
                    for (int it = 0; it < 8; ++it) {
                        const int dl = dl0 + 32 * it;
                        float4 g = *(const float4*)(W + (size_t)(nt * 256 + dl) * RR + rt * 32 + f4 * 4);
                        st[(f4 * 4 + 0) * SHP + dl] = g.x;
                        st[(f4 * 4 + 1) * SHP + dl] = g.y;
                        st[(f4 * 4 + 2) * SHP + dl] = g.z;
                        st[(f4 * 4 + 3) * SHP + dl] = g.w;
                    }
                }
                __syncthreads();

                const float* shb = sh + (bq * 4) * SHP + rt * 32;
                #pragma unroll
                for (int rr2 = 0; rr2 < 32; ++rr2) {
                    const float a0 = shb[0 * SHP + rr2];
                    const float a1 = shb[1 * SHP + rr2];
                    const float a2 = shb[2 * SHP + rr2];
                    const float a3 = shb[3 * SHP + rr2];
                    const float* str = st + rr2 * SHP + lq;
                    #pragma unroll
                    for (int i = 0; i < 8; ++i) {
                        const float w = str[32 * i];
                        acc2[0][i] += a0 * w;
                        acc2[1][i] += a1 * w;
                        acc2[2][i] += a2 * w;
                        acc2[3][i] += a3 * w;
                    }
                }
                __syncthreads();
            }

            // elementwise update: v += dcoef * (force - Gamma); fold x accumulation
            #pragma unroll
            for (int j = 0; j < 4; ++j) {
                const int b    = bq * 4 + j;
                const size_t grow = (size_t)(row0 + b) * DD;
                #pragma unroll
                for (int i = 0; i < 8; ++i) {
                    const int d = nt * 256 + lq + 32 * i;
                    const float g    = force[grow + d];
                    const float a    = g - acc2[j][i];
                    const float vold = sv[b * DD + d];
                    const float vnew = vold + dcoef * a;
                    sv[b * DD + d] = vnew;

                    float* ox = out + grow + d;   // x-region used as accumulator
                    if (step == 0) {
                        *ox = K_C1 * vold + K_C2 * vnew;           // C1*v0 + C2*v1
                    } else if (step == 1) {
                        *ox = *ox + K_C2 * vnew;                   // + C3*v2  (C3==C2)
                    } else {
                        const float xa = *ox + K_C1 * vnew;        // + C4*v3  (C4==C1)
                        *ox = x[grow + d] + K_DT * xa;             // x_final
                        out[(size_t)BB * DD + grow + d] = vnew;    // v3
                    }
                }
            }
            __syncthreads();
        }
    }
}

extern "C" void kernel_launch(void* const* d_in, const int* in_sizes, int n_in,
                              void* d_out, int out_size)
{
    const float* x     = (const float*)d_in[0];
    const float* v     = (const float*)d_in[1];
    const float* force = (const float*)d_in[2];
    const float* U     = (const float*)d_in[3];
    const float* W     = (const float*)d_in[4];
    float* out = (float*)d_out;

    const size_t smem_bytes = (size_t)(TM * DD + TM * SHP + 32 * SHP) * sizeof(float);
    cudaFuncSetAttribute(yoshida_fused_kernel,
                         cudaFuncAttributeMaxDynamicSharedMemorySize, (int)smem_bytes);

    yoshida_fused_kernel<<<NCTA, NTHR, smem_bytes>>>(x, v, force, U, W, out);
}